// round 7
// baseline (speedup 1.0000x reference)
#include <cuda_runtime.h>
#include <cuda_bf16.h>

#define M_SEG 16
#define ITEMS 4          // float4 per thread, block-contiguous tile
#define NTHREADS 256

// Warp-0 computes the 16 affine coefficients (c0,c1) into shared:
//   out = c0[j] + c1[j]*S,   j = floor(S*16) clamped to [0,15]
__device__ __forceinline__ void build_coeffs(float2* sc, const float* __restrict__ u)
{
    int t = threadIdx.x;
    if (t < 32) {
        int lane = t;
        float uu = __ldg(&u[lane & (M_SEG - 1)]);
        float sig = 1.0f / (1.0f + __expf(-uu));
        float a = 0.5f + 4.5f * sig;                 // A_MIN + (A_MAX-A_MIN)*sigmoid
        float seg = (lane < M_SEG) ? a * (1.0f / M_SEG) : 0.0f;

        // inclusive scan over lanes 0..15
        float v = seg;
        #pragma unroll
        for (int off = 1; off < M_SEG; off <<= 1) {
            float nb = __shfl_up_sync(0xffffffffu, v, off);
            if (lane >= off) v += nb;
        }
        float Y = __shfl_sync(0xffffffffu, v, M_SEG - 1);
        float invY = 1.0f / Y;
        if (lane < M_SEG) {
            float excl = v - seg;
            float c1 = a * invY;
            float c0 = (excl - a * (float)lane * (1.0f / M_SEG)) * invY;
            sc[lane] = make_float2(c0, c1);
        }
    }
    __syncthreads();
}

__device__ __forceinline__ float map_one(float s, const float2* sc)
{
    int j = (int)(s * (float)M_SEG);                 // exact: bounds are k/16
    j = min(max(j, 0), M_SEG - 1);
    float2 c = sc[j];
    return fmaf(c.y, s, c.x);
}

__device__ __forceinline__ float4 map_vec(float4 v, const float2* sc)
{
    float4 r;
    r.x = map_one(v.x, sc);
    r.y = map_one(v.y, sc);
    r.z = map_one(v.z, sc);
    r.w = map_one(v.w, sc);
    return r;
}

// One-shot kernel: each block maps a contiguous tile of ITEMS*NTHREADS float4
// (16 KB). All ITEMS loads per thread are independent and front-batched.
__global__ void __launch_bounds__(NTHREADS) map_kernel(const float4* __restrict__ S,
                                                       float4* __restrict__ out,
                                                       int n4,
                                                       const float* __restrict__ u)
{
    __shared__ float2 sc[M_SEG];
    build_coeffs(sc, u);

    const int base = blockIdx.x * (NTHREADS * ITEMS) + threadIdx.x;

    int idx[ITEMS];
    bool p[ITEMS];
    float4 v[ITEMS];

    #pragma unroll
    for (int k = 0; k < ITEMS; ++k) {
        idx[k] = base + k * NTHREADS;                // block-local, contiguous tile
        p[k] = idx[k] < n4;
    }
    #pragma unroll
    for (int k = 0; k < ITEMS; ++k) {
        if (p[k]) v[k] = __ldcs(&S[idx[k]]);
    }
    #pragma unroll
    for (int k = 0; k < ITEMS; ++k) {
        if (p[k]) __stcs(&out[idx[k]], map_vec(v[k], sc));
    }
}

// Scalar tail (only launched when n % 4 != 0)
__global__ void __launch_bounds__(256) map_tail_kernel(const float* __restrict__ S,
                                                       float* __restrict__ out,
                                                       int start, int n,
                                                       const float* __restrict__ u)
{
    __shared__ float2 sc[M_SEG];
    build_coeffs(sc, u);
    int i = start + blockIdx.x * blockDim.x + threadIdx.x;
    if (i < n) out[i] = map_one(S[i], sc);
}

extern "C" void kernel_launch(void* const* d_in, const int* in_sizes, int n_in,
                              void* d_out, int out_size)
{
    const float* S = (const float*)d_in[0];
    const float* u = (const float*)d_in[1];
    float* out = (float*)d_out;

    int n = in_sizes[0];
    int n4 = n / 4;

    if (n4 > 0) {
        const int per_block = NTHREADS * ITEMS;
        int blocks = (n4 + per_block - 1) / per_block;
        map_kernel<<<blocks, NTHREADS>>>((const float4*)S, (float4*)out, n4, u);
    }
    int tail = n - n4 * 4;
    if (tail > 0) {
        map_tail_kernel<<<1, 256>>>(S, out, n4 * 4, n, u);
    }
}

// round 10
// speedup vs baseline: 1.1535x; 1.1535x over previous
#include <cuda_runtime.h>
#include <cuda_bf16.h>

#define M_SEG 16
#define NTHREADS 256

// Warp-0 computes the 16 affine coefficients (c0,c1) into shared:
//   out = c0[j] + c1[j]*S,   j = floor(S*16) clamped to [0,15]
//   c1[j] = a[j]/Y,  c0[j] = (cum_excl[j] - a[j]*j/16)/Y
__device__ __forceinline__ void build_coeffs(float2* sc, const float* __restrict__ u)
{
    int t = threadIdx.x;
    if (t < 32) {
        int lane = t;
        float uu = __ldg(&u[lane & (M_SEG - 1)]);
        float sig = 1.0f / (1.0f + __expf(-uu));
        float a = 0.5f + 4.5f * sig;                 // A_MIN + (A_MAX-A_MIN)*sigmoid
        float seg = (lane < M_SEG) ? a * (1.0f / M_SEG) : 0.0f;

        // inclusive scan over lanes 0..15
        float v = seg;
        #pragma unroll
        for (int off = 1; off < M_SEG; off <<= 1) {
            float nb = __shfl_up_sync(0xffffffffu, v, off);
            if (lane >= off) v += nb;
        }
        float Y = __shfl_sync(0xffffffffu, v, M_SEG - 1);
        float invY = 1.0f / Y;
        if (lane < M_SEG) {
            float excl = v - seg;
            float c1 = a * invY;
            float c0 = (excl - a * (float)lane * (1.0f / M_SEG)) * invY;
            sc[lane] = make_float2(c0, c1);
        }
    }
    __syncthreads();
}

__device__ __forceinline__ float map_one(float s, const float2* sc)
{
    int j = (int)(s * (float)M_SEG);                 // exact: bounds are k/16
    j = min(max(j, 0), M_SEG - 1);
    float2 c = sc[j];
    return fmaf(c.y, s, c.x);
}

__device__ __forceinline__ float4 map_vec(float4 v, const float2* sc)
{
    float4 r;
    r.x = map_one(v.x, sc);
    r.y = map_one(v.y, sc);
    r.z = map_one(v.z, sc);
    r.w = map_one(v.w, sc);
    return r;
}

// One-shot: each thread handles 2 float4, grid-wide item stride (streams far
// apart -> disjoint L2 slices, no L1tex queue interference), front-batched.
__global__ void __launch_bounds__(NTHREADS) map_kernel(const float4* __restrict__ S,
                                                       float4* __restrict__ out,
                                                       int n4,
                                                       const float* __restrict__ u)
{
    __shared__ float2 sc[M_SEG];
    build_coeffs(sc, u);

    int stride = gridDim.x * NTHREADS;
    int i0 = blockIdx.x * NTHREADS + threadIdx.x;
    int i1 = i0 + stride;

    bool p0 = i0 < n4;
    bool p1 = i1 < n4;
    float4 v0, v1;
    if (p0) v0 = __ldcs(&S[i0]);
    if (p1) v1 = __ldcs(&S[i1]);

    if (p0) __stcs(&out[i0], map_vec(v0, sc));
    if (p1) __stcs(&out[i1], map_vec(v1, sc));
}

// Scalar tail (only launched when n % 4 != 0)
__global__ void __launch_bounds__(256) map_tail_kernel(const float* __restrict__ S,
                                                       float* __restrict__ out,
                                                       int start, int n,
                                                       const float* __restrict__ u)
{
    __shared__ float2 sc[M_SEG];
    build_coeffs(sc, u);
    int i = start + blockIdx.x * blockDim.x + threadIdx.x;
    if (i < n) out[i] = map_one(S[i], sc);
}

extern "C" void kernel_launch(void* const* d_in, const int* in_sizes, int n_in,
                              void* d_out, int out_size)
{
    const float* S = (const float*)d_in[0];
    const float* u = (const float*)d_in[1];
    float* out = (float*)d_out;

    int n = in_sizes[0];
    int n4 = n / 4;

    if (n4 > 0) {
        const int per_block = NTHREADS * 2;          // 2 float4 per thread
        int blocks = (n4 + per_block - 1) / per_block;
        map_kernel<<<blocks, NTHREADS>>>((const float4*)S, (float4*)out, n4, u);
    }
    int tail = n - n4 * 4;
    if (tail > 0) {
        map_tail_kernel<<<1, 256>>>(S, out, n4 * 4, n, u);
    }
}

// round 12
// speedup vs baseline: 1.1934x; 1.0346x over previous
#include <cuda_runtime.h>
#include <cuda_bf16.h>

#define M_SEG 16
#define NTHREADS 256

// Warp-0 computes the 16 affine coefficients (c0,c1) into shared:
//   out = c0[j] + c1[j]*S,   j = floor(S*16) clamped to [0,15]
//   c1[j] = a[j]/Y,  c0[j] = (cum_excl[j] - a[j]*j/16)/Y
__device__ __forceinline__ void build_coeffs(float2* sc, const float* __restrict__ u)
{
    int t = threadIdx.x;
    if (t < 32) {
        int lane = t;
        float uu = __ldg(&u[lane & (M_SEG - 1)]);
        float sig = 1.0f / (1.0f + __expf(-uu));
        float a = 0.5f + 4.5f * sig;                 // A_MIN + (A_MAX-A_MIN)*sigmoid
        float seg = (lane < M_SEG) ? a * (1.0f / M_SEG) : 0.0f;

        // inclusive scan over lanes 0..15
        float v = seg;
        #pragma unroll
        for (int off = 1; off < M_SEG; off <<= 1) {
            float nb = __shfl_up_sync(0xffffffffu, v, off);
            if (lane >= off) v += nb;
        }
        float Y = __shfl_sync(0xffffffffu, v, M_SEG - 1);
        float invY = 1.0f / Y;
        if (lane < M_SEG) {
            float excl = v - seg;
            float c1 = a * invY;
            float c0 = (excl - a * (float)lane * (1.0f / M_SEG)) * invY;
            sc[lane] = make_float2(c0, c1);
        }
    }
    __syncthreads();
}

__device__ __forceinline__ float map_one(float s, const float2* sc)
{
    int j = (int)(s * (float)M_SEG);                 // exact: bounds are k/16
    j = min(max(j, 0), M_SEG - 1);
    float2 c = sc[j];
    return fmaf(c.y, s, c.x);
}

__device__ __forceinline__ float4 map_vec(float4 v, const float2* sc)
{
    float4 r;
    r.x = map_one(v.x, sc);
    r.y = map_one(v.y, sc);
    r.z = map_one(v.z, sc);
    r.w = map_one(v.w, sc);
    return r;
}

// One-shot: each thread handles 2 float4 with grid-wide item stride (the two
// streams are ~32MB apart -> disjoint L2 slices), loads front-batched.
// Best-measured configuration (R4): default cache operators.
__global__ void __launch_bounds__(NTHREADS) map_kernel(const float4* __restrict__ S,
                                                       float4* __restrict__ out,
                                                       int n4,
                                                       const float* __restrict__ u)
{
    __shared__ float2 sc[M_SEG];
    build_coeffs(sc, u);

    int stride = gridDim.x * NTHREADS;
    int i0 = blockIdx.x * NTHREADS + threadIdx.x;
    int i1 = i0 + stride;

    bool p0 = i0 < n4;
    bool p1 = i1 < n4;
    float4 v0, v1;
    if (p0) v0 = S[i0];
    if (p1) v1 = S[i1];

    if (p0) out[i0] = map_vec(v0, sc);
    if (p1) out[i1] = map_vec(v1, sc);
}

// Scalar tail (only launched when n % 4 != 0)
__global__ void __launch_bounds__(256) map_tail_kernel(const float* __restrict__ S,
                                                       float* __restrict__ out,
                                                       int start, int n,
                                                       const float* __restrict__ u)
{
    __shared__ float2 sc[M_SEG];
    build_coeffs(sc, u);
    int i = start + blockIdx.x * blockDim.x + threadIdx.x;
    if (i < n) out[i] = map_one(S[i], sc);
}

extern "C" void kernel_launch(void* const* d_in, const int* in_sizes, int n_in,
                              void* d_out, int out_size)
{
    const float* S = (const float*)d_in[0];
    const float* u = (const float*)d_in[1];
    float* out = (float*)d_out;

    int n = in_sizes[0];
    int n4 = n / 4;

    if (n4 > 0) {
        const int per_block = NTHREADS * 2;          // 2 float4 per thread
        int blocks = (n4 + per_block - 1) / per_block;
        map_kernel<<<blocks, NTHREADS>>>((const float4*)S, (float4*)out, n4, u);
    }
    int tail = n - n4 * 4;
    if (tail > 0) {
        map_tail_kernel<<<1, 256>>>(S, out, n4 * 4, n, u);
    }
}